// round 15
// baseline (speedup 1.0000x reference)
#include <cuda_runtime.h>
#include <cuda_fp16.h>
#include <cstdint>
#include <cstddef>

// Problem constants
#define BQ 4
#define SEQ 1024
#define DEMB 1024
#define NHEAD 16
#define DRED 64
#define NTOK (BQ*SEQ)          // 4096
#define DFFN (4*DEMB)          // 4096
#define BHSR ((size_t)BQ*NHEAD*SEQ*DRED)   // 4M

// ---------------------------------------------------------------------------
// Scratch (static device memory; no allocations anywhere)
// ---------------------------------------------------------------------------
__device__ float  g_res [(size_t)NTOK*DEMB];
__device__ float  g_ln1 [(size_t)NTOK*DEMB];
__device__ float  g_ln2 [(size_t)NTOK*DEMB];
__device__ __half g_xh  [(size_t)NTOK*DEMB];
__device__ __half g_ctxh[(size_t)NTOK*DEMB];
__device__ __half g_ln1h[(size_t)NTOK*DEMB];
__device__ __half g_ln2h[(size_t)NTOK*DEMB];
__device__ __half g_atth[(size_t)NTOK*DEMB];
__device__ __half g_ffnh[(size_t)NTOK*DFFN];
__device__ __half g_qkvh[(size_t)3*BHSR];

// fp16 weight scratch: transposed [N,K].
#define WME (1024*1024)
__device__ __half g_wh[(size_t)16*WME];

// ---------------------------------------------------------------------------
// PTX helpers (baseline PTX only)
// ---------------------------------------------------------------------------
__device__ __forceinline__ uint32_t smem_to_u32(const void* p) {
    uint32_t a;
    asm("{ .reg .u64 t; cvta.to.shared.u64 t, %1; cvt.u32.u64 %0, t; }"
        : "=r"(a) : "l"(p));
    return a;
}
__device__ __forceinline__ void cp_async16(uint32_t s, const void* g) {
    asm volatile("cp.async.cg.shared.global [%0], [%1], 16;" :: "r"(s), "l"(g));
}
#define CP_COMMIT() asm volatile("cp.async.commit_group;" ::: "memory")
#define CP_WAIT0()  asm volatile("cp.async.wait_group 0;" ::: "memory")

__device__ __forceinline__ void ldm_x4(uint32_t* r, uint32_t addr) {
    asm volatile("ldmatrix.sync.aligned.m8n8.x4.shared.b16 {%0,%1,%2,%3}, [%4];"
        : "=r"(r[0]), "=r"(r[1]), "=r"(r[2]), "=r"(r[3]) : "r"(addr));
}
__device__ __forceinline__ void ldm_x4_t(uint32_t* r, uint32_t addr) {
    asm volatile("ldmatrix.sync.aligned.m8n8.x4.trans.shared.b16 {%0,%1,%2,%3}, [%4];"
        : "=r"(r[0]), "=r"(r[1]), "=r"(r[2]), "=r"(r[3]) : "r"(addr));
}
__device__ __forceinline__ void mma_f16(float* c, const uint32_t* a,
                                        uint32_t b0, uint32_t b1) {
    asm volatile(
        "mma.sync.aligned.m16n8k16.row.col.f32.f16.f16.f32 "
        "{%0,%1,%2,%3}, {%4,%5,%6,%7}, {%8,%9}, {%0,%1,%2,%3};"
        : "+f"(c[0]), "+f"(c[1]), "+f"(c[2]), "+f"(c[3])
        : "r"(a[0]), "r"(a[1]), "r"(a[2]), "r"(a[3]), "r"(b0), "r"(b1));
}
__device__ __forceinline__ uint32_t pack_h2(float x, float y) {
    __half2 h = __floats2half2_rn(x, y);
    return *(uint32_t*)&h;
}

// ---------------------------------------------------------------------------
// Fused fp32 -> fp16 elementwise for x and ctx
// ---------------------------------------------------------------------------
__global__ __launch_bounds__(256)
void conv_h2(const float* __restrict__ a, const float* __restrict__ b,
             __half* __restrict__ oa, __half* __restrict__ ob)
{
    const float* in  = blockIdx.y ? b : a;
    __half* out      = blockIdx.y ? ob : oa;
    const size_t i = ((size_t)blockIdx.x * 256 + threadIdx.x) * 4;
    float4 v = *(const float4*)&in[i];
    *(__half2*)&out[i]     = __floats2half2_rn(v.x, v.y);
    *(__half2*)&out[i + 2] = __floats2half2_rn(v.z, v.w);
}

// ---------------------------------------------------------------------------
// Weight transpose + fp16 convert, generic [R,C] per z-block.
// ---------------------------------------------------------------------------
__global__ __launch_bounds__(256)
void wconv(const float* __restrict__ in, __half* __restrict__ oh, int R, int C)
{
    __shared__ float tile[32][33];
    const int bz = blockIdx.z;
    const float* ip = in + (size_t)bz * R * C;
    const int r0 = blockIdx.y * 32, c0 = blockIdx.x * 32;
    const int tx = threadIdx.x & 31;
    const int ty = threadIdx.x >> 5;

    #pragma unroll
    for (int i = 0; i < 32; i += 8)
        tile[ty + i][tx] = ip[(size_t)(r0 + ty + i) * C + c0 + tx];
    __syncthreads();

    #pragma unroll
    for (int i = 0; i < 32; i += 8) {
        float x = tile[tx][ty + i];
        size_t o = ((size_t)bz * C + c0 + ty + i) * R + r0 + tx;
        oh[o] = __float2half_rn(x);
    }
}

// Fused 2-matrix wconv (sa_wo + ca_wo, both 1024x1024)
__global__ __launch_bounds__(256)
void wconv2(const float* __restrict__ in0, const float* __restrict__ in1,
            __half* __restrict__ o0, __half* __restrict__ o1)
{
    __shared__ float tile[32][33];
    const float* in = blockIdx.z ? in1 : in0;
    __half* oh      = blockIdx.z ? o1  : o0;
    const int R = 1024, C = 1024;
    const int r0 = blockIdx.y * 32, c0 = blockIdx.x * 32;
    const int tx = threadIdx.x & 31;
    const int ty = threadIdx.x >> 5;

    #pragma unroll
    for (int i = 0; i < 32; i += 8)
        tile[ty + i][tx] = in[(size_t)(r0 + ty + i) * C + c0 + tx];
    __syncthreads();

    #pragma unroll
    for (int i = 0; i < 32; i += 8) {
        float x = tile[tx][ty + i];
        size_t o = ((size_t)(c0 + ty + i)) * R + r0 + tx;
        oh[o] = __float2half_rn(x);
    }
}

// Fused 6-way wconv for both QKV triples ([H,D,R], H=16 blocks of 1024x64)
__global__ __launch_bounds__(256)
void wconv6(const float* __restrict__ w0, const float* __restrict__ w1,
            const float* __restrict__ w2, const float* __restrict__ w3,
            const float* __restrict__ w4, const float* __restrict__ w5,
            __half* __restrict__ oh)
{
    __shared__ float tile[32][33];
    const int z   = blockIdx.z;            // 0..95
    const int grp = z >> 4;                // 0..5
    const int bz  = z & 15;
    const float* in = (grp == 0) ? w0 : (grp == 1) ? w1 : (grp == 2) ? w2
                    : (grp == 3) ? w3 : (grp == 4) ? w4 : w5;
    __half* out = oh + (size_t)((grp < 3) ? grp : grp + 1) * WME;
    const int R = 1024, C = 64;
    const float* ip = in + (size_t)bz * R * C;
    const int r0 = blockIdx.y * 32, c0 = blockIdx.x * 32;
    const int tx = threadIdx.x & 31;
    const int ty = threadIdx.x >> 5;

    #pragma unroll
    for (int i = 0; i < 32; i += 8)
        tile[ty + i][tx] = ip[(size_t)(r0 + ty + i) * C + c0 + tx];
    __syncthreads();

    #pragma unroll
    for (int i = 0; i < 32; i += 8) {
        float x = tile[tx][ty + i];
        size_t o = ((size_t)bz * C + c0 + ty + i) * R + r0 + tx;
        out[o] = __float2half_rn(x);
    }
}

// ---------------------------------------------------------------------------
// Tensor-core GEMM (fp16 in, fp32 accumulate).
// CTA tile 128x128 (grids IDENTICAL to R12), 128 threads, 4 warps of 64x64.
// Fragment duplication A x2, B x2 -> smem reads 48KB -> 32KB per chunk.
// R8-proven schedule: issue c+1 -> compute c -> wait -> sync.
// OMODE 0: fp32 row-major.  1: fused-QKV fp16 [3][B,H,S,R].  2: fp16 row-major.
// ---------------------------------------------------------------------------
#define PITCH 80
#define OFF_W  10240
#define BUFSZ  20480
#define GSMEM  (2*BUFSZ)
#define GT     128

template<int OMODE, bool RESID, bool RELU>
__global__ __launch_bounds__(GT)
void tgemm(const __half* __restrict__ A0, const __half* __restrict__ A1,
           const __half* __restrict__ A2, const __half* __restrict__ W,
           const float* __restrict__ b0, const float* __restrict__ b1,
           const float* __restrict__ b2, const float* __restrict__ resid,
           void* __restrict__ Cout, int M, int N, int K)
{
    extern __shared__ char smem[];
    const uint32_t sb = smem_to_u32(smem);

    const int t    = threadIdx.x;
    const int lane = t & 31;
    const int wid  = t >> 5;        // 0..3
    const int wm   = wid >> 1;      // 0..1 (64 rows)
    const int wn   = wid & 1;       // 0..1 (64 cols)
    const int m0   = blockIdx.y * 128;
    const int n0   = blockIdx.x * 128;
    const int nch  = K >> 5;

    const int which = (OMODE == 1) ? (n0 >> 10) : 0;
    const __half* A   = (which == 0) ? A0 : (which == 1) ? A1 : A2;
    const float* bias = (which == 0) ? b0 : (which == 1) ? b1 : b2;

    // staging: thread t stages full 64B row t of A and of W
    const uint32_t rDst = (uint32_t)t * PITCH;
    const __half*  aSrcBase = A + (size_t)(m0 + t) * K;
    const __half*  wSrcBase = W + (size_t)(n0 + t) * K;

    float acc[4][8][4];
    #pragma unroll
    for (int a = 0; a < 4; a++)
        #pragma unroll
        for (int b = 0; b < 8; b++)
            #pragma unroll
            for (int d = 0; d < 4; d++) acc[a][b][d] = 0.f;

    auto loadAW = [&](int k0, uint32_t bufo) {
        #pragma unroll
        for (int i = 0; i < 4; i++) {
            cp_async16(sb + bufo + rDst + i * 16,         aSrcBase + k0 + i * 8);
            cp_async16(sb + bufo + OFF_W + rDst + i * 16, wSrcBase + k0 + i * 8);
        }
        CP_COMMIT();
    };

    const uint32_t aBase = sb + (uint32_t)(wm * 64 + (lane & 15)) * PITCH + (lane >> 4) * 16;
    const uint32_t wBase = sb + OFF_W
        + (uint32_t)(wn * 64 + ((lane >> 4) << 3) + (lane & 7)) * PITCH
        + ((lane >> 3) & 1) * 16;

    auto compute = [&](uint32_t bufo) {
        #pragma unroll
        for (int ks = 0; ks < 2; ks++) {
            uint32_t ah[4][4];
            #pragma unroll
            for (int mt = 0; mt < 4; mt++)
                ldm_x4(ah[mt], aBase + bufo + mt * (16*PITCH) + ks * 32);
            #pragma unroll
            for (int ng = 0; ng < 2; ng++) {
                uint32_t bh[8];
                #pragma unroll
                for (int p = 0; p < 2; p++)
                    ldm_x4(bh + p*4, wBase + bufo + (ng*2 + p) * (16*PITCH) + ks * 32);
                #pragma unroll
                for (int nt = 0; nt < 4; nt++)
                    #pragma unroll
                    for (int mt = 0; mt < 4; mt++)
                        mma_f16(acc[mt][ng*4 + nt], ah[mt], bh[nt*2], bh[nt*2+1]);
            }
        }
    };

    loadAW(0, 0);
    CP_WAIT0();
    __syncthreads();

    for (int c = 0; c < nch; c++) {
        const uint32_t bufo = (c & 1) * BUFSZ;
        const bool hasNext = (c + 1 < nch);
        if (hasNext) loadAW((c + 1) << 5, BUFSZ - bufo);
        compute(bufo);
        if (hasNext) CP_WAIT0();
        __syncthreads();
    }

    // ---- epilogue ----
    #pragma unroll
    for (int mt = 0; mt < 4; mt++) {
        const int m = m0 + wm * 64 + mt * 16 + (lane >> 2);
        #pragma unroll
        for (int j = 0; j < 8; j++) {
            const int n = n0 + wn * 64 + j * 8 + (lane & 3) * 2;
            const int nb = (OMODE == 1) ? (n & 1023) : n;
            float2 v0 = make_float2(acc[mt][j][0], acc[mt][j][1]);
            float2 v1 = make_float2(acc[mt][j][2], acc[mt][j][3]);
            float2 b2v = *(const float2*)&bias[nb];
            v0.x += b2v.x; v0.y += b2v.y;
            v1.x += b2v.x; v1.y += b2v.y;
            if (RESID) {
                float2 r0 = *(const float2*)&resid[(size_t)m * N + n];
                float2 r1 = *(const float2*)&resid[(size_t)(m + 8) * N + n];
                v0.x += r0.x; v0.y += r0.y;
                v1.x += r1.x; v1.y += r1.y;
            }
            if (RELU) {
                v0.x = fmaxf(v0.x, 0.f); v0.y = fmaxf(v0.y, 0.f);
                v1.x = fmaxf(v1.x, 0.f); v1.y = fmaxf(v1.y, 0.f);
            }
            if (OMODE == 0) {
                float* C = (float*)Cout;
                *(float2*)&C[(size_t)m * N + n]       = v0;
                *(float2*)&C[(size_t)(m + 8) * N + n] = v1;
            } else if (OMODE == 2) {
                __half* C = (__half*)Cout;
                *(__half2*)&C[(size_t)m * N + n]       = __floats2half2_rn(v0.x, v0.y);
                *(__half2*)&C[(size_t)(m + 8) * N + n] = __floats2half2_rn(v1.x, v1.y);
            } else {
                __half* C = (__half*)Cout;
                const int h = nb >> 6, r = nb & 63;
                size_t o0 = (size_t)which * BHSR
                          + ((size_t)((m >> 10) * NHEAD + h) * SEQ + (m & (SEQ-1))) * DRED + r;
                size_t o1 = (size_t)which * BHSR
                          + ((size_t)(((m+8) >> 10) * NHEAD + h) * SEQ + ((m+8) & (SEQ-1))) * DRED + r;
                *(__half2*)&C[o0] = __floats2half2_rn(v0.x, v0.y);
                *(__half2*)&C[o1] = __floats2half2_rn(v1.x, v1.y);
            }
        }
    }
}

// ---------------------------------------------------------------------------
// Tensor-core flash attention (fp16 in/out) — R12 version (Q-hoisted).
// ---------------------------------------------------------------------------
#define APITCH 144
#define SQ_OFF 0
#define SK_OFF 18432
#define SV_OFF 36864
#define ASMEM  55296

__global__ __launch_bounds__(256)
void attn_tc(const __half* __restrict__ QKV, __half* __restrict__ Out)
{
    extern __shared__ char sm[];
    const uint32_t sb = smem_to_u32(sm);

    const int t    = threadIdx.x;
    const int lane = t & 31;
    const int w    = t >> 5;
    const int bh   = blockIdx.y;
    const int b    = bh >> 4;
    const int h    = bh & 15;
    const int q0   = blockIdx.x * 128;

    const size_t base = (size_t)bh * SEQ * DRED;
    const __half* Qb = QKV + base;
    const __half* Kb = QKV + BHSR + base;
    const __half* Vb = QKV + 2 * BHSR + base;

    const int lrow  = t >> 1;
    const int lhalf = t & 1;
    auto stage = [&](const __half* src, uint32_t dst) {
        const __half* g = src + (size_t)lrow * DRED + lhalf * 32;
        uint32_t d = sb + dst + (uint32_t)lrow * APITCH + lhalf * 64;
        cp_async16(d,      g);
        cp_async16(d + 16, g + 8);
        cp_async16(d + 32, g + 16);
        cp_async16(d + 48, g + 24);
    };

    stage(Qb + (size_t)q0 * DRED, SQ_OFF);
    CP_COMMIT();

    const uint32_t aOff = (uint32_t)(w * 16 + (lane & 15)) * APITCH + (lane >> 4) * 16;
    const uint32_t kRow = ((lane >> 4) << 3) + (lane & 7);
    const uint32_t kCol = ((lane >> 3) & 1) * 16;

    // hoist Q fragments (loop-invariant): 4 x ldm_x4 = 16 regs
    uint32_t qh[4][4];
    {
        CP_WAIT0();
        __syncthreads();
        #pragma unroll
        for (int ks = 0; ks < 4; ks++)
            ldm_x4(qh[ks], sb + SQ_OFF + aOff + ks * 32);
        __syncthreads();
    }

    float S[16][4];
    float O[8][4];
    float m0 = -1e30f, m1 = -1e30f, l0 = 0.f, l1 = 0.f;
    #pragma unroll
    for (int j = 0; j < 8; j++)
        #pragma unroll
        for (int d = 0; d < 4; d++) O[j][d] = 0.f;

    for (int kt = 0; kt < SEQ / 128; kt++) {
        __syncthreads();
        stage(Kb + (size_t)(kt * 128) * DRED, SK_OFF);
        stage(Vb + (size_t)(kt * 128) * DRED, SV_OFF);
        CP_COMMIT();
        CP_WAIT0();
        __syncthreads();

        // ---- S = Q K^T ----
        #pragma unroll
        for (int j = 0; j < 16; j++) {
            S[j][0] = 0.f; S[j][1] = 0.f; S[j][2] = 0.f; S[j][3] = 0.f;
        }
        #pragma unroll
        for (int ks = 0; ks < 4; ks++) {
            #pragma unroll
            for (int np = 0; np < 8; np++) {
                uint32_t off = (uint32_t)(np * 16 + kRow) * APITCH + kCol + ks * 32;
                uint32_t bh4[4];
                ldm_x4(bh4, sb + SK_OFF + off);
                #pragma unroll
                for (int nt = 0; nt < 2; nt++)
                    mma_f16(S[np * 2 + nt], qh[ks], bh4[nt*2], bh4[nt*2+1]);
            }
        }

        // ---- online softmax ----
        float mx0 = -1e30f, mx1 = -1e30f;
        #pragma unroll
        for (int j = 0; j < 16; j++) {
            S[j][0] *= 0.125f; S[j][1] *= 0.125f;
            S[j][2] *= 0.125f; S[j][3] *= 0.125f;
            mx0 = fmaxf(mx0, fmaxf(S[j][0], S[j][1]));
            mx1 = fmaxf(mx1, fmaxf(S[j][2], S[j][3]));
        }
        mx0 = fmaxf(mx0, __shfl_xor_sync(0xffffffffu, mx0, 1));
        mx0 = fmaxf(mx0, __shfl_xor_sync(0xffffffffu, mx0, 2));
        mx1 = fmaxf(mx1, __shfl_xor_sync(0xffffffffu, mx1, 1));
        mx1 = fmaxf(mx1, __shfl_xor_sync(0xffffffffu, mx1, 2));
        float mn0 = fmaxf(m0, mx0), mn1 = fmaxf(m1, mx1);
        float a0 = __expf(m0 - mn0), a1 = __expf(m1 - mn1);
        m0 = mn0; m1 = mn1;
        float rs0 = 0.f, rs1 = 0.f;
        #pragma unroll
        for (int j = 0; j < 16; j++) {
            float p0 = __expf(S[j][0] - mn0); S[j][0] = p0; rs0 += p0;
            float p1 = __expf(S[j][1] - mn0); S[j][1] = p1; rs0 += p1;
            float p2 = __expf(S[j][2] - mn1); S[j][2] = p2; rs1 += p2;
            float p3 = __expf(S[j][3] - mn1); S[j][3] = p3; rs1 += p3;
        }
        l0 = l0 * a0 + rs0;
        l1 = l1 * a1 + rs1;
        #pragma unroll
        for (int j = 0; j < 8; j++) {
            O[j][0] *= a0; O[j][1] *= a0;
            O[j][2] *= a1; O[j][3] *= a1;
        }

        // ---- O += P V ----
        #pragma unroll
        for (int ks = 0; ks < 8; ks++) {
            uint32_t ah[4];
            ah[0] = pack_h2(S[2*ks][0],   S[2*ks][1]);
            ah[1] = pack_h2(S[2*ks][2],   S[2*ks][3]);
            ah[2] = pack_h2(S[2*ks+1][0], S[2*ks+1][1]);
            ah[3] = pack_h2(S[2*ks+1][2], S[2*ks+1][3]);
            #pragma unroll
            for (int np = 0; np < 4; np++) {
                uint32_t off = (uint32_t)(ks * 16 + ((lane >> 3) & 1) * 8 + (lane & 7)) * APITCH
                             + (np * 16 + (lane >> 4) * 8) * 2;
                uint32_t bh4[4];
                ldm_x4_t(bh4, sb + SV_OFF + off);
                #pragma unroll
                for (int nt = 0; nt < 2; nt++)
                    mma_f16(O[np * 2 + nt], ah, bh4[nt*2], bh4[nt*2+1]);
            }
        }
    }

    // ---- finalize ----
    l0 += __shfl_xor_sync(0xffffffffu, l0, 1);
    l0 += __shfl_xor_sync(0xffffffffu, l0, 2);
    l1 += __shfl_xor_sync(0xffffffffu, l1, 1);
    l1 += __shfl_xor_sync(0xffffffffu, l1, 2);
    const float inv0 = 1.f / l0, inv1 = 1.f / l1;

    const int r0 = q0 + w * 16 + (lane >> 2);
    const size_t tok0 = (size_t)b * SEQ + r0;
    const size_t tok1 = tok0 + 8;
    #pragma unroll
    for (int ng = 0; ng < 8; ng++) {
        const int col = h * DRED + ng * 8 + (lane & 3) * 2;
        *(__half2*)&Out[tok0 * DEMB + col] = __floats2half2_rn(O[ng][0] * inv0, O[ng][1] * inv0);
        *(__half2*)&Out[tok1 * DEMB + col] = __floats2half2_rn(O[ng][2] * inv1, O[ng][3] * inv1);
    }
}

// ---------------------------------------------------------------------------
// LayerNorm over rows of 1024, eps = 1e-3; optional dual fp16 write
// ---------------------------------------------------------------------------
template<bool DUALH>
__global__ __launch_bounds__(256)
void ln_kernel(const float* __restrict__ in, const float* __restrict__ gam,
               const float* __restrict__ bet, float* __restrict__ out,
               __half* __restrict__ outh)
{
    __shared__ float red[16];
    const int row = blockIdx.x;
    const int t   = threadIdx.x;
    const float* p = in + (size_t)row * DEMB;

    float4 v = *(const float4*)&p[t * 4];
    float s  = v.x + v.y + v.z + v.w;
    float ss = v.x * v.x + v.y * v.y + v.z * v.z + v.w * v.w;
    #pragma unroll
    for (int o = 16; o >= 1; o >>= 1) {
        s  += __shfl_xor_sync(0xffffffffu, s, o);
        ss += __shfl_xor_sync(0xffffffffu, ss, o);
    }
    if ((t & 31) == 0) { red[t >> 5] = s; red[8 + (t >> 5)] = ss; }
    __syncthreads();
    s = 0.f; ss = 0.f;
    #pragma unroll
    for (int i = 0; i < 8; i++) { s += red[i]; ss += red[8 + i]; }

    float mean = s * (1.f / DEMB);
    float var  = ss * (1.f / DEMB) - mean * mean;
    float r    = rsqrtf(var + 1e-3f);

    float4 g4 = *(const float4*)&gam[t * 4];
    float4 b4 = *(const float4*)&bet[t * 4];
    float4 o;
    o.x = (v.x - mean) * r * g4.x + b4.x;
    o.y = (v.y - mean) * r * g4.y + b4.y;
    o.z = (v.z - mean) * r * g4.z + b4.z;
    o.w = (v.w - mean) * r * g4.w + b4.w;
    *(float4*)&out[(size_t)row * DEMB + t * 4] = o;
    if (DUALH) {
        *(__half2*)&outh[(size_t)row * DEMB + t * 4]     = __floats2half2_rn(o.x, o.y);
        *(__half2*)&outh[(size_t)row * DEMB + t * 4 + 2] = __floats2half2_rn(o.z, o.w);
    }
}

// ---------------------------------------------------------------------------
// Launch
// ---------------------------------------------------------------------------
extern "C" void kernel_launch(void* const* d_in, const int* in_sizes, int n_in,
                              void* d_out, int out_size)
{
    const float* x      = (const float*)d_in[0];
    const float* ctx    = (const float*)d_in[1];
    const float* sa_wq  = (const float*)d_in[2];
    const float* sa_bq  = (const float*)d_in[3];
    const float* sa_wk  = (const float*)d_in[4];
    const float* sa_bk  = (const float*)d_in[5];
    const float* sa_wv  = (const float*)d_in[6];
    const float* sa_bv  = (const float*)d_in[7];
    const float* sa_wo  = (const float*)d_in[8];
    const float* sa_bo  = (const float*)d_in[9];
    const float* ca_wq  = (const float*)d_in[10];
    const float* ca_bq  = (const float*)d_in[11];
    const float* ca_wk  = (const float*)d_in[12];
    const float* ca_bk  = (const float*)d_in[13];
    const float* ca_wv  = (const float*)d_in[14];
    const float* ca_bv  = (const float*)d_in[15];
    const float* ca_wo  = (const float*)d_in[16];
    const float* ca_bo  = (const float*)d_in[17];
    const float* ln1_g  = (const float*)d_in[18];
    const float* ln1_b  = (const float*)d_in[19];
    const float* ln2_g  = (const float*)d_in[20];
    const float* ln2_b  = (const float*)d_in[21];
    const float* ln3_g  = (const float*)d_in[22];
    const float* ln3_b  = (const float*)d_in[23];
    const float* ffn_w1 = (const float*)d_in[24];
    const float* ffn_b1 = (const float*)d_in[25];
    const float* ffn_w2 = (const float*)d_in[26];
    const float* ffn_b2 = (const float*)d_in[27];
    float* out = (float*)d_out;

    float *res, *ln1, *ln2;
    __half *xh, *ctxh, *ln1h, *ln2h, *atth, *ffnh, *qkvh, *wh;
    cudaGetSymbolAddress((void**)&res,  g_res);
    cudaGetSymbolAddress((void**)&ln1,  g_ln1);
    cudaGetSymbolAddress((void**)&ln2,  g_ln2);
    cudaGetSymbolAddress((void**)&xh,   g_xh);
    cudaGetSymbolAddress((void**)&ctxh, g_ctxh);
    cudaGetSymbolAddress((void**)&ln1h, g_ln1h);
    cudaGetSymbolAddress((void**)&ln2h, g_ln2h);
    cudaGetSymbolAddress((void**)&atth, g_atth);
    cudaGetSymbolAddress((void**)&ffnh, g_ffnh);
    cudaGetSymbolAddress((void**)&qkvh, g_qkvh);
    cudaGetSymbolAddress((void**)&wh,   g_wh);

    cudaFuncSetAttribute(tgemm<1, false, false>, cudaFuncAttributeMaxDynamicSharedMemorySize, GSMEM);
    cudaFuncSetAttribute(tgemm<0, true,  false>, cudaFuncAttributeMaxDynamicSharedMemorySize, GSMEM);
    cudaFuncSetAttribute(tgemm<2, false, true >, cudaFuncAttributeMaxDynamicSharedMemorySize, GSMEM);
    cudaFuncSetAttribute(attn_tc, cudaFuncAttributeMaxDynamicSharedMemorySize, ASMEM);

    // ---- conversions (5 launches) ----
    dim3 gc(NTOK * DEMB / 1024, 2);
    conv_h2<<<gc, 256>>>(x, ctx, xh, ctxh);
    dim3 tp6(2, 32, 96);
    wconv6<<<tp6, 256>>>(sa_wq, sa_wk, sa_wv, ca_wq, ca_wk, ca_wv, wh);
    dim3 tpO(32, 32, 2);
    wconv2<<<tpO, 256>>>(sa_wo, ca_wo, wh + (size_t)3*WME, wh + (size_t)7*WME);
    dim3 tpF1(128, 32, 1);
    wconv<<<tpF1, 256>>>(ffn_w1, wh + (size_t)8*WME,  1024, 4096);
    dim3 tpF2(32, 128, 1);
    wconv<<<tpF2, 256>>>(ffn_w2, wh + (size_t)12*WME, 4096, 1024);

    dim3 gQKV(3 * DEMB / 128, NTOK / 128);   // (24, 32)  — same as R12
    dim3 gProj(DEMB / 128, NTOK / 128);      // (8, 32)
    dim3 gFfn1(DFFN / 128, NTOK / 128);      // (32, 32)
    dim3 gAttn(SEQ / 128, BQ * NHEAD);       // (8, 64)

    // ---- self attention ----
    tgemm<1, false, false><<<gQKV, GT, GSMEM>>>(xh, xh, xh, wh + (size_t)0*WME,
        sa_bq, sa_bk, sa_bv, nullptr, qkvh, NTOK, 3*DEMB, DEMB);
    attn_tc<<<gAttn, 256, ASMEM>>>(qkvh, atth);
    tgemm<0, true, false><<<gProj, GT, GSMEM>>>(atth, atth, atth, wh + (size_t)3*WME,
        sa_bo, sa_bo, sa_bo, x, res, NTOK, DEMB, DEMB);
    ln_kernel<true><<<NTOK, 256>>>(res, ln1_g, ln1_b, ln1, ln1h);

    // ---- cross attention ----
    tgemm<1, false, false><<<gQKV, GT, GSMEM>>>(ln1h, ctxh, ctxh, wh + (size_t)4*WME,
        ca_bq, ca_bk, ca_bv, nullptr, qkvh, NTOK, 3*DEMB, DEMB);
    attn_tc<<<gAttn, 256, ASMEM>>>(qkvh, atth);
    tgemm<0, true, false><<<gProj, GT, GSMEM>>>(atth, atth, atth, wh + (size_t)7*WME,
        ca_bo, ca_bo, ca_bo, ln1, res, NTOK, DEMB, DEMB);
    ln_kernel<true><<<NTOK, 256>>>(res, ln2_g, ln2_b, ln2, ln2h);

    // ---- FFN ----
    tgemm<2, false, true><<<gFfn1, GT, GSMEM>>>(ln2h, ln2h, ln2h, wh + (size_t)8*WME,
        ffn_b1, ffn_b1, ffn_b1, nullptr, ffnh, NTOK, DFFN, DEMB);
    tgemm<0, true, false><<<gProj, GT, GSMEM>>>(ffnh, ffnh, ffnh, wh + (size_t)12*WME,
        ffn_b2, ffn_b2, ffn_b2, ln2, res, NTOK, DEMB, DFFN);
    ln_kernel<false><<<NTOK, 256>>>(res, ln3_g, ln3_b, out, nullptr);
}

// round 16
// speedup vs baseline: 1.2632x; 1.2632x over previous
#include <cuda_runtime.h>
#include <cuda_fp16.h>
#include <cstdint>
#include <cstddef>

// Problem constants
#define BQ 4
#define SEQ 1024
#define DEMB 1024
#define NHEAD 16
#define DRED 64
#define NTOK (BQ*SEQ)          // 4096
#define DFFN (4*DEMB)          // 4096
#define BHSR ((size_t)BQ*NHEAD*SEQ*DRED)   // 4M

// ---------------------------------------------------------------------------
// Scratch (static device memory; no allocations anywhere)
// ---------------------------------------------------------------------------
__device__ float  g_res [(size_t)NTOK*DEMB];
__device__ float  g_ln1 [(size_t)NTOK*DEMB];
__device__ float  g_ln2 [(size_t)NTOK*DEMB];
__device__ __half g_xh  [(size_t)NTOK*DEMB];
__device__ __half g_ctxh[(size_t)NTOK*DEMB];
__device__ __half g_ln1h[(size_t)NTOK*DEMB];
__device__ __half g_ln2h[(size_t)NTOK*DEMB];
__device__ __half g_atth[(size_t)NTOK*DEMB];
__device__ __half g_ffnh[(size_t)NTOK*DFFN];
__device__ __half g_qkvh[(size_t)3*BHSR];

// fp16 weight scratch: transposed [N,K].
#define WME (1024*1024)
__device__ __half g_wh[(size_t)16*WME];

// ---------------------------------------------------------------------------
// PTX helpers (baseline PTX only)
// ---------------------------------------------------------------------------
__device__ __forceinline__ uint32_t smem_to_u32(const void* p) {
    uint32_t a;
    asm("{ .reg .u64 t; cvta.to.shared.u64 t, %1; cvt.u32.u64 %0, t; }"
        : "=r"(a) : "l"(p));
    return a;
}
__device__ __forceinline__ void cp_async16(uint32_t s, const void* g) {
    asm volatile("cp.async.cg.shared.global [%0], [%1], 16;" :: "r"(s), "l"(g));
}
#define CP_COMMIT() asm volatile("cp.async.commit_group;" ::: "memory")
#define CP_WAIT0()  asm volatile("cp.async.wait_group 0;" ::: "memory")
#define CP_WAIT1()  asm volatile("cp.async.wait_group 1;" ::: "memory")

__device__ __forceinline__ void ldm_x4(uint32_t* r, uint32_t addr) {
    asm volatile("ldmatrix.sync.aligned.m8n8.x4.shared.b16 {%0,%1,%2,%3}, [%4];"
        : "=r"(r[0]), "=r"(r[1]), "=r"(r[2]), "=r"(r[3]) : "r"(addr));
}
__device__ __forceinline__ void ldm_x4_t(uint32_t* r, uint32_t addr) {
    asm volatile("ldmatrix.sync.aligned.m8n8.x4.trans.shared.b16 {%0,%1,%2,%3}, [%4];"
        : "=r"(r[0]), "=r"(r[1]), "=r"(r[2]), "=r"(r[3]) : "r"(addr));
}
__device__ __forceinline__ void mma_f16(float* c, const uint32_t* a,
                                        uint32_t b0, uint32_t b1) {
    asm volatile(
        "mma.sync.aligned.m16n8k16.row.col.f32.f16.f16.f32 "
        "{%0,%1,%2,%3}, {%4,%5,%6,%7}, {%8,%9}, {%0,%1,%2,%3};"
        : "+f"(c[0]), "+f"(c[1]), "+f"(c[2]), "+f"(c[3])
        : "r"(a[0]), "r"(a[1]), "r"(a[2]), "r"(a[3]), "r"(b0), "r"(b1));
}
__device__ __forceinline__ uint32_t pack_h2(float x, float y) {
    __half2 h = __floats2half2_rn(x, y);
    return *(uint32_t*)&h;
}

// ---------------------------------------------------------------------------
// Fused fp32 -> fp16 elementwise for x and ctx
// ---------------------------------------------------------------------------
__global__ __launch_bounds__(256)
void conv_h2(const float* __restrict__ a, const float* __restrict__ b,
             __half* __restrict__ oa, __half* __restrict__ ob)
{
    const float* in  = blockIdx.y ? b : a;
    __half* out      = blockIdx.y ? ob : oa;
    const size_t i = ((size_t)blockIdx.x * 256 + threadIdx.x) * 4;
    float4 v = *(const float4*)&in[i];
    *(__half2*)&out[i]     = __floats2half2_rn(v.x, v.y);
    *(__half2*)&out[i + 2] = __floats2half2_rn(v.z, v.w);
}

// ---------------------------------------------------------------------------
// Weight transpose + fp16 convert, generic [R,C] per z-block.
// ---------------------------------------------------------------------------
__global__ __launch_bounds__(256)
void wconv(const float* __restrict__ in, __half* __restrict__ oh, int R, int C)
{
    __shared__ float tile[32][33];
    const int bz = blockIdx.z;
    const float* ip = in + (size_t)bz * R * C;
    const int r0 = blockIdx.y * 32, c0 = blockIdx.x * 32;
    const int tx = threadIdx.x & 31;
    const int ty = threadIdx.x >> 5;

    #pragma unroll
    for (int i = 0; i < 32; i += 8)
        tile[ty + i][tx] = ip[(size_t)(r0 + ty + i) * C + c0 + tx];
    __syncthreads();

    #pragma unroll
    for (int i = 0; i < 32; i += 8) {
        float x = tile[tx][ty + i];
        size_t o = ((size_t)bz * C + c0 + ty + i) * R + r0 + tx;
        oh[o] = __float2half_rn(x);
    }
}

// Fused 2-matrix wconv (sa_wo + ca_wo, both 1024x1024)
__global__ __launch_bounds__(256)
void wconv2(const float* __restrict__ in0, const float* __restrict__ in1,
            __half* __restrict__ o0, __half* __restrict__ o1)
{
    __shared__ float tile[32][33];
    const float* in = blockIdx.z ? in1 : in0;
    __half* oh      = blockIdx.z ? o1  : o0;
    const int R = 1024, C = 1024;
    const int r0 = blockIdx.y * 32, c0 = blockIdx.x * 32;
    const int tx = threadIdx.x & 31;
    const int ty = threadIdx.x >> 5;

    #pragma unroll
    for (int i = 0; i < 32; i += 8)
        tile[ty + i][tx] = in[(size_t)(r0 + ty + i) * C + c0 + tx];
    __syncthreads();

    #pragma unroll
    for (int i = 0; i < 32; i += 8) {
        float x = tile[tx][ty + i];
        size_t o = ((size_t)(c0 + ty + i)) * R + r0 + tx;
        oh[o] = __float2half_rn(x);
    }
}

// Fused 6-way wconv for both QKV triples ([H,D,R], H=16 blocks of 1024x64)
__global__ __launch_bounds__(256)
void wconv6(const float* __restrict__ w0, const float* __restrict__ w1,
            const float* __restrict__ w2, const float* __restrict__ w3,
            const float* __restrict__ w4, const float* __restrict__ w5,
            __half* __restrict__ oh)
{
    __shared__ float tile[32][33];
    const int z   = blockIdx.z;            // 0..95
    const int grp = z >> 4;                // 0..5
    const int bz  = z & 15;
    const float* in = (grp == 0) ? w0 : (grp == 1) ? w1 : (grp == 2) ? w2
                    : (grp == 3) ? w3 : (grp == 4) ? w4 : w5;
    __half* out = oh + (size_t)((grp < 3) ? grp : grp + 1) * WME;
    const int R = 1024, C = 64;
    const float* ip = in + (size_t)bz * R * C;
    const int r0 = blockIdx.y * 32, c0 = blockIdx.x * 32;
    const int tx = threadIdx.x & 31;
    const int ty = threadIdx.x >> 5;

    #pragma unroll
    for (int i = 0; i < 32; i += 8)
        tile[ty + i][tx] = ip[(size_t)(r0 + ty + i) * C + c0 + tx];
    __syncthreads();

    #pragma unroll
    for (int i = 0; i < 32; i += 8) {
        float x = tile[tx][ty + i];
        size_t o = ((size_t)bz * C + c0 + ty + i) * R + r0 + tx;
        out[o] = __float2half_rn(x);
    }
}

// ---------------------------------------------------------------------------
// Tensor-core GEMM (fp16 in, fp32 accumulate) — EXACT R12 version (best).
// CTA 128x128, 256 threads, 8 warps of 32x64, BK=32, 2 x 20KB buffers.
// Schedule: issue c+1 -> compute c -> wait -> sync.
// OMODE 0: fp32 row-major.  1: fused-QKV fp16 [3][B,H,S,R].  2: fp16 row-major.
// ---------------------------------------------------------------------------
#define PITCH 80
#define OFF_W  10240
#define BUFSZ  20480
#define GSMEM  (2*BUFSZ)

template<int OMODE, bool RESID, bool RELU>
__global__ __launch_bounds__(256)
void tgemm(const __half* __restrict__ A0, const __half* __restrict__ A1,
           const __half* __restrict__ A2, const __half* __restrict__ W,
           const float* __restrict__ b0, const float* __restrict__ b1,
           const float* __restrict__ b2, const float* __restrict__ resid,
           void* __restrict__ Cout, int M, int N, int K)
{
    extern __shared__ char smem[];
    const uint32_t sb = smem_to_u32(smem);

    const int t    = threadIdx.x;
    const int lane = t & 31;
    const int wid  = t >> 5;
    const int wm   = wid & 3;
    const int wn   = wid >> 2;
    const int m0   = blockIdx.y * 128;
    const int n0   = blockIdx.x * 128;
    const int nch  = K >> 5;

    const int which = (OMODE == 1) ? (n0 >> 10) : 0;
    const __half* A   = (which == 0) ? A0 : (which == 1) ? A1 : A2;
    const float* bias = (which == 0) ? b0 : (which == 1) ? b1 : b2;

    // A staging: row t>>1, 32B half (t&1)
    const uint32_t aDst = (uint32_t)(t >> 1) * PITCH + (t & 1) * 32;
    const __half*  aSrcBase = A + (size_t)(m0 + (t >> 1)) * K + (t & 1) * 16;
    // W staging: 2 16B chunks per thread
    const int q0r = (2 * t) >> 2,     q0c = (2 * t) & 3;
    const int q1r = (2 * t + 1) >> 2, q1c = (2 * t + 1) & 3;

    float acc[2][8][4];
    #pragma unroll
    for (int a = 0; a < 2; a++)
        #pragma unroll
        for (int b = 0; b < 8; b++)
            #pragma unroll
            for (int d = 0; d < 4; d++) acc[a][b][d] = 0.f;

    auto loadAW = [&](int k0, uint32_t bufo) {
        cp_async16(sb + bufo + aDst,      aSrcBase + k0);
        cp_async16(sb + bufo + aDst + 16, aSrcBase + k0 + 8);
        cp_async16(sb + bufo + OFF_W + q0r * PITCH + q0c * 16,
                   W + (size_t)(n0 + q0r) * K + k0 + q0c * 8);
        cp_async16(sb + bufo + OFF_W + q1r * PITCH + q1c * 16,
                   W + (size_t)(n0 + q1r) * K + k0 + q1c * 8);
        CP_COMMIT();
    };

    const uint32_t aBase = sb + (uint32_t)(wm * 32 + (lane & 15)) * PITCH + (lane >> 4) * 16;
    const uint32_t wBase = sb + OFF_W
        + (uint32_t)(wn * 64 + ((lane >> 4) << 3) + (lane & 7)) * PITCH
        + ((lane >> 3) & 1) * 16;

    auto compute = [&](uint32_t bufo) {
        #pragma unroll
        for (int ks = 0; ks < 2; ks++) {
            uint32_t ah[2][4];
            #pragma unroll
            for (int mt = 0; mt < 2; mt++)
                ldm_x4(ah[mt], aBase + bufo + mt * (16*PITCH) + ks * 32);
            #pragma unroll
            for (int ng = 0; ng < 2; ng++) {
                uint32_t bh[8];
                #pragma unroll
                for (int p = 0; p < 2; p++)
                    ldm_x4(bh + p*4, wBase + bufo + (ng*2 + p) * (16*PITCH) + ks * 32);
                #pragma unroll
                for (int nt = 0; nt < 4; nt++)
                    #pragma unroll
                    for (int mt = 0; mt < 2; mt++)
                        mma_f16(acc[mt][ng*4 + nt], ah[mt], bh[nt*2], bh[nt*2+1]);
            }
        }
    };

    loadAW(0, 0);
    CP_WAIT0();
    __syncthreads();

    for (int c = 0; c < nch; c++) {
        const uint32_t bufo = (c & 1) * BUFSZ;
        const bool hasNext = (c + 1 < nch);
        if (hasNext) loadAW((c + 1) << 5, BUFSZ - bufo);
        compute(bufo);
        if (hasNext) CP_WAIT0();
        __syncthreads();
    }

    // ---- epilogue ----
    #pragma unroll
    for (int mt = 0; mt < 2; mt++) {
        const int m = m0 + wm * 32 + mt * 16 + (lane >> 2);
        #pragma unroll
        for (int j = 0; j < 8; j++) {
            const int n = n0 + wn * 64 + j * 8 + (lane & 3) * 2;
            const int nb = (OMODE == 1) ? (n & 1023) : n;
            float2 v0 = make_float2(acc[mt][j][0], acc[mt][j][1]);
            float2 v1 = make_float2(acc[mt][j][2], acc[mt][j][3]);
            float2 b2v = *(const float2*)&bias[nb];
            v0.x += b2v.x; v0.y += b2v.y;
            v1.x += b2v.x; v1.y += b2v.y;
            if (RESID) {
                float2 r0 = *(const float2*)&resid[(size_t)m * N + n];
                float2 r1 = *(const float2*)&resid[(size_t)(m + 8) * N + n];
                v0.x += r0.x; v0.y += r0.y;
                v1.x += r1.x; v1.y += r1.y;
            }
            if (RELU) {
                v0.x = fmaxf(v0.x, 0.f); v0.y = fmaxf(v0.y, 0.f);
                v1.x = fmaxf(v1.x, 0.f); v1.y = fmaxf(v1.y, 0.f);
            }
            if (OMODE == 0) {
                float* C = (float*)Cout;
                *(float2*)&C[(size_t)m * N + n]       = v0;
                *(float2*)&C[(size_t)(m + 8) * N + n] = v1;
            } else if (OMODE == 2) {
                __half* C = (__half*)Cout;
                *(__half2*)&C[(size_t)m * N + n]       = __floats2half2_rn(v0.x, v0.y);
                *(__half2*)&C[(size_t)(m + 8) * N + n] = __floats2half2_rn(v1.x, v1.y);
            } else {
                __half* C = (__half*)Cout;
                const int h = nb >> 6, r = nb & 63;
                size_t o0 = (size_t)which * BHSR
                          + ((size_t)((m >> 10) * NHEAD + h) * SEQ + (m & (SEQ-1))) * DRED + r;
                size_t o1 = (size_t)which * BHSR
                          + ((size_t)(((m+8) >> 10) * NHEAD + h) * SEQ + ((m+8) & (SEQ-1))) * DRED + r;
                *(__half2*)&C[o0] = __floats2half2_rn(v0.x, v0.y);
                *(__half2*)&C[o1] = __floats2half2_rn(v1.x, v1.y);
            }
        }
    }
}

// ---------------------------------------------------------------------------
// Tensor-core flash attention (fp16 in/out), Q-hoisted + double-buffered K/V.
// Q,K,V: [B,H,S,R] fp16.  Out: fp16 [B*S, H*R].  Grid (S/128, B*H), 256 thr.
// smem: Q (18432) + 2 x (K 18432 + V 18432) = 92160.
// ---------------------------------------------------------------------------
#define APITCH 144
#define AKV    36864
#define ASMEM  92160

__global__ __launch_bounds__(256)
void attn_tc(const __half* __restrict__ QKV, __half* __restrict__ Out)
{
    extern __shared__ char sm[];
    const uint32_t sb = smem_to_u32(sm);

    const int t    = threadIdx.x;
    const int lane = t & 31;
    const int w    = t >> 5;
    const int bh   = blockIdx.y;
    const int b    = bh >> 4;
    const int h    = bh & 15;
    const int q0   = blockIdx.x * 128;

    const size_t base = (size_t)bh * SEQ * DRED;
    const __half* Qb = QKV + base;
    const __half* Kb = QKV + BHSR + base;
    const __half* Vb = QKV + 2 * BHSR + base;

    const int lrow  = t >> 1;
    const int lhalf = t & 1;
    auto stage = [&](const __half* src, uint32_t dst) {
        const __half* g = src + (size_t)lrow * DRED + lhalf * 32;
        uint32_t d = sb + dst + (uint32_t)lrow * APITCH + lhalf * 64;
        cp_async16(d,      g);
        cp_async16(d + 16, g + 8);
        cp_async16(d + 32, g + 16);
        cp_async16(d + 48, g + 24);
    };
    auto stageKV = [&](int kt, int buf) {
        uint32_t o = 18432 + (uint32_t)buf * AKV;
        stage(Kb + (size_t)(kt * 128) * DRED, o);
        stage(Vb + (size_t)(kt * 128) * DRED, o + 18432);
        CP_COMMIT();
    };

    // stage Q, wait, hoist fragments (loop-invariant, 16 regs)
    stage(Qb + (size_t)q0 * DRED, 0);
    CP_COMMIT();

    const uint32_t aOff = (uint32_t)(w * 16 + (lane & 15)) * APITCH + (lane >> 4) * 16;
    const uint32_t kRow = ((lane >> 4) << 3) + (lane & 7);
    const uint32_t kCol = ((lane >> 3) & 1) * 16;

    uint32_t qh[4][4];
    {
        CP_WAIT0();
        __syncthreads();
        #pragma unroll
        for (int ks = 0; ks < 4; ks++)
            ldm_x4(qh[ks], sb + aOff + ks * 32);
        __syncthreads();
    }

    // prologue: first KV tile
    stageKV(0, 0);

    float S[16][4];
    float O[8][4];
    float m0 = -1e30f, m1 = -1e30f, l0 = 0.f, l1 = 0.f;
    #pragma unroll
    for (int j = 0; j < 8; j++)
        #pragma unroll
        for (int d = 0; d < 4; d++) O[j][d] = 0.f;

    for (int kt = 0; kt < SEQ / 128; kt++) {
        const int buf = kt & 1;
        if (kt + 1 < SEQ / 128) {
            stageKV(kt + 1, buf ^ 1);
            CP_WAIT1();
        } else {
            CP_WAIT0();
        }
        __syncthreads();

        const uint32_t SK = 18432 + (uint32_t)buf * AKV;
        const uint32_t SV = SK + 18432;

        // ---- S = Q K^T ----
        #pragma unroll
        for (int j = 0; j < 16; j++) {
            S[j][0] = 0.f; S[j][1] = 0.f; S[j][2] = 0.f; S[j][3] = 0.f;
        }
        #pragma unroll
        for (int ks = 0; ks < 4; ks++) {
            #pragma unroll
            for (int np = 0; np < 8; np++) {
                uint32_t off = (uint32_t)(np * 16 + kRow) * APITCH + kCol + ks * 32;
                uint32_t bh4[4];
                ldm_x4(bh4, sb + SK + off);
                #pragma unroll
                for (int nt = 0; nt < 2; nt++)
                    mma_f16(S[np * 2 + nt], qh[ks], bh4[nt*2], bh4[nt*2+1]);
            }
        }

        // ---- online softmax ----
        float mx0 = -1e30f, mx1 = -1e30f;
        #pragma unroll
        for (int j = 0; j < 16; j++) {
            S[j][0] *= 0.125f; S[j][1] *= 0.125f;
            S[j][2] *= 0.125f; S[j][3] *= 0.125f;
            mx0 = fmaxf(mx0, fmaxf(S[j][0], S[j][1]));
            mx1 = fmaxf(mx1, fmaxf(S[j][2], S[j][3]));
        }
        mx0 = fmaxf(mx0, __shfl_xor_sync(0xffffffffu, mx0, 1));
        mx0 = fmaxf(mx0, __shfl_xor_sync(0xffffffffu, mx0, 2));
        mx1 = fmaxf(mx1, __shfl_xor_sync(0xffffffffu, mx1, 1));
        mx1 = fmaxf(mx1, __shfl_xor_sync(0xffffffffu, mx1, 2));
        float mn0 = fmaxf(m0, mx0), mn1 = fmaxf(m1, mx1);
        float a0 = __expf(m0 - mn0), a1 = __expf(m1 - mn1);
        m0 = mn0; m1 = mn1;
        float rs0 = 0.f, rs1 = 0.f;
        #pragma unroll
        for (int j = 0; j < 16; j++) {
            float p0 = __expf(S[j][0] - mn0); S[j][0] = p0; rs0 += p0;
            float p1 = __expf(S[j][1] - mn0); S[j][1] = p1; rs0 += p1;
            float p2 = __expf(S[j][2] - mn1); S[j][2] = p2; rs1 += p2;
            float p3 = __expf(S[j][3] - mn1); S[j][3] = p3; rs1 += p3;
        }
        l0 = l0 * a0 + rs0;
        l1 = l1 * a1 + rs1;
        #pragma unroll
        for (int j = 0; j < 8; j++) {
            O[j][0] *= a0; O[j][1] *= a0;
            O[j][2] *= a1; O[j][3] *= a1;
        }

        // ---- O += P V ----
        #pragma unroll
        for (int ks = 0; ks < 8; ks++) {
            uint32_t ah[4];
            ah[0] = pack_h2(S[2*ks][0],   S[2*ks][1]);
            ah[1] = pack_h2(S[2*ks][2],   S[2*ks][3]);
            ah[2] = pack_h2(S[2*ks+1][0], S[2*ks+1][1]);
            ah[3] = pack_h2(S[2*ks+1][2], S[2*ks+1][3]);
            #pragma unroll
            for (int np = 0; np < 4; np++) {
                uint32_t off = (uint32_t)(ks * 16 + ((lane >> 3) & 1) * 8 + (lane & 7)) * APITCH
                             + (np * 16 + (lane >> 4) * 8) * 2;
                uint32_t bh4[4];
                ldm_x4_t(bh4, sb + SV + off);
                #pragma unroll
                for (int nt = 0; nt < 2; nt++)
                    mma_f16(O[np * 2 + nt], ah, bh4[nt*2], bh4[nt*2+1]);
            }
        }
        __syncthreads();   // all warps done reading buf before it's restaged
    }

    // ---- finalize ----
    l0 += __shfl_xor_sync(0xffffffffu, l0, 1);
    l0 += __shfl_xor_sync(0xffffffffu, l0, 2);
    l1 += __shfl_xor_sync(0xffffffffu, l1, 1);
    l1 += __shfl_xor_sync(0xffffffffu, l1, 2);
    const float inv0 = 1.f / l0, inv1 = 1.f / l1;

    const int r0 = q0 + w * 16 + (lane >> 2);
    const size_t tok0 = (size_t)b * SEQ + r0;
    const size_t tok1 = tok0 + 8;
    #pragma unroll
    for (int ng = 0; ng < 8; ng++) {
        const int col = h * DRED + ng * 8 + (lane & 3) * 2;
        *(__half2*)&Out[tok0 * DEMB + col] = __floats2half2_rn(O[ng][0] * inv0, O[ng][1] * inv0);
        *(__half2*)&Out[tok1 * DEMB + col] = __floats2half2_rn(O[ng][2] * inv1, O[ng][3] * inv1);
    }
}

// ---------------------------------------------------------------------------
// LayerNorm over rows of 1024, eps = 1e-3; optional dual fp16 write
// ---------------------------------------------------------------------------
template<bool DUALH>
__global__ __launch_bounds__(256)
void ln_kernel(const float* __restrict__ in, const float* __restrict__ gam,
               const float* __restrict__ bet, float* __restrict__ out,
               __half* __restrict__ outh)
{
    __shared__ float red[16];
    const int row = blockIdx.x;
    const int t   = threadIdx.x;
    const float* p = in + (size_t)row * DEMB;

    float4 v = *(const float4*)&p[t * 4];
    float s  = v.x + v.y + v.z + v.w;
    float ss = v.x * v.x + v.y * v.y + v.z * v.z + v.w * v.w;
    #pragma unroll
    for (int o = 16; o >= 1; o >>= 1) {
        s  += __shfl_xor_sync(0xffffffffu, s, o);
        ss += __shfl_xor_sync(0xffffffffu, ss, o);
    }
    if ((t & 31) == 0) { red[t >> 5] = s; red[8 + (t >> 5)] = ss; }
    __syncthreads();
    s = 0.f; ss = 0.f;
    #pragma unroll
    for (int i = 0; i < 8; i++) { s += red[i]; ss += red[8 + i]; }

    float mean = s * (1.f / DEMB);
    float var  = ss * (1.f / DEMB) - mean * mean;
    float r    = rsqrtf(var + 1e-3f);

    float4 g4 = *(const float4*)&gam[t * 4];
    float4 b4 = *(const float4*)&bet[t * 4];
    float4 o;
    o.x = (v.x - mean) * r * g4.x + b4.x;
    o.y = (v.y - mean) * r * g4.y + b4.y;
    o.z = (v.z - mean) * r * g4.z + b4.z;
    o.w = (v.w - mean) * r * g4.w + b4.w;
    *(float4*)&out[(size_t)row * DEMB + t * 4] = o;
    if (DUALH) {
        *(__half2*)&outh[(size_t)row * DEMB + t * 4]     = __floats2half2_rn(o.x, o.y);
        *(__half2*)&outh[(size_t)row * DEMB + t * 4 + 2] = __floats2half2_rn(o.z, o.w);
    }
}

// ---------------------------------------------------------------------------
// Launch
// ---------------------------------------------------------------------------
extern "C" void kernel_launch(void* const* d_in, const int* in_sizes, int n_in,
                              void* d_out, int out_size)
{
    const float* x      = (const float*)d_in[0];
    const float* ctx    = (const float*)d_in[1];
    const float* sa_wq  = (const float*)d_in[2];
    const float* sa_bq  = (const float*)d_in[3];
    const float* sa_wk  = (const float*)d_in[4];
    const float* sa_bk  = (const float*)d_in[5];
    const float* sa_wv  = (const float*)d_in[6];
    const float* sa_bv  = (const float*)d_in[7];
    const float* sa_wo  = (const float*)d_in[8];
    const float* sa_bo  = (const float*)d_in[9];
    const float* ca_wq  = (const float*)d_in[10];
    const float* ca_bq  = (const float*)d_in[11];
    const float* ca_wk  = (const float*)d_in[12];
    const float* ca_bk  = (const float*)d_in[13];
    const float* ca_wv  = (const float*)d_in[14];
    const float* ca_bv  = (const float*)d_in[15];
    const float* ca_wo  = (const float*)d_in[16];
    const float* ca_bo  = (const float*)d_in[17];
    const float* ln1_g  = (const float*)d_in[18];
    const float* ln1_b  = (const float*)d_in[19];
    const float* ln2_g  = (const float*)d_in[20];
    const float* ln2_b  = (const float*)d_in[21];
    const float* ln3_g  = (const float*)d_in[22];
    const float* ln3_b  = (const float*)d_in[23];
    const float* ffn_w1 = (const float*)d_in[24];
    const float* ffn_b1 = (const float*)d_in[25];
    const float* ffn_w2 = (const float*)d_in[26];
    const float* ffn_b2 = (const float*)d_in[27];
    float* out = (float*)d_out;

    float *res, *ln1, *ln2;
    __half *xh, *ctxh, *ln1h, *ln2h, *atth, *ffnh, *qkvh, *wh;
    cudaGetSymbolAddress((void**)&res,  g_res);
    cudaGetSymbolAddress((void**)&ln1,  g_ln1);
    cudaGetSymbolAddress((void**)&ln2,  g_ln2);
    cudaGetSymbolAddress((void**)&xh,   g_xh);
    cudaGetSymbolAddress((void**)&ctxh, g_ctxh);
    cudaGetSymbolAddress((void**)&ln1h, g_ln1h);
    cudaGetSymbolAddress((void**)&ln2h, g_ln2h);
    cudaGetSymbolAddress((void**)&atth, g_atth);
    cudaGetSymbolAddress((void**)&ffnh, g_ffnh);
    cudaGetSymbolAddress((void**)&qkvh, g_qkvh);
    cudaGetSymbolAddress((void**)&wh,   g_wh);

    cudaFuncSetAttribute(tgemm<1, false, false>, cudaFuncAttributeMaxDynamicSharedMemorySize, GSMEM);
    cudaFuncSetAttribute(tgemm<0, true,  false>, cudaFuncAttributeMaxDynamicSharedMemorySize, GSMEM);
    cudaFuncSetAttribute(tgemm<2, false, true >, cudaFuncAttributeMaxDynamicSharedMemorySize, GSMEM);
    cudaFuncSetAttribute(attn_tc, cudaFuncAttributeMaxDynamicSharedMemorySize, ASMEM);

    // ---- conversions (5 launches) ----
    dim3 gc(NTOK * DEMB / 1024, 2);
    conv_h2<<<gc, 256>>>(x, ctx, xh, ctxh);
    dim3 tp6(2, 32, 96);
    wconv6<<<tp6, 256>>>(sa_wq, sa_wk, sa_wv, ca_wq, ca_wk, ca_wv, wh);
    dim3 tpO(32, 32, 2);
    wconv2<<<tpO, 256>>>(sa_wo, ca_wo, wh + (size_t)3*WME, wh + (size_t)7*WME);
    dim3 tpF1(128, 32, 1);
    wconv<<<tpF1, 256>>>(ffn_w1, wh + (size_t)8*WME,  1024, 4096);
    dim3 tpF2(32, 128, 1);
    wconv<<<tpF2, 256>>>(ffn_w2, wh + (size_t)12*WME, 4096, 1024);

    dim3 gQKV(3 * DEMB / 128, NTOK / 128);   // (24, 32)
    dim3 gProj(DEMB / 128, NTOK / 128);      // (8, 32)
    dim3 gFfn1(DFFN / 128, NTOK / 128);      // (32, 32)
    dim3 gAttn(SEQ / 128, BQ * NHEAD);       // (8, 64)

    // ---- self attention ----
    tgemm<1, false, false><<<gQKV, 256, GSMEM>>>(xh, xh, xh, wh + (size_t)0*WME,
        sa_bq, sa_bk, sa_bv, nullptr, qkvh, NTOK, 3*DEMB, DEMB);
    attn_tc<<<gAttn, 256, ASMEM>>>(qkvh, atth);
    tgemm<0, true, false><<<gProj, 256, GSMEM>>>(atth, atth, atth, wh + (size_t)3*WME,
        sa_bo, sa_bo, sa_bo, x, res, NTOK, DEMB, DEMB);
    ln_kernel<true><<<NTOK, 256>>>(res, ln1_g, ln1_b, ln1, ln1h);

    // ---- cross attention ----
    tgemm<1, false, false><<<gQKV, 256, GSMEM>>>(ln1h, ctxh, ctxh, wh + (size_t)4*WME,
        ca_bq, ca_bk, ca_bv, nullptr, qkvh, NTOK, 3*DEMB, DEMB);
    attn_tc<<<gAttn, 256, ASMEM>>>(qkvh, atth);
    tgemm<0, true, false><<<gProj, 256, GSMEM>>>(atth, atth, atth, wh + (size_t)7*WME,
        ca_bo, ca_bo, ca_bo, ln1, res, NTOK, DEMB, DEMB);
    ln_kernel<true><<<NTOK, 256>>>(res, ln2_g, ln2_b, ln2, ln2h);

    // ---- FFN ----
    tgemm<2, false, true><<<gFfn1, 256, GSMEM>>>(ln2h, ln2h, ln2h, wh + (size_t)8*WME,
        ffn_b1, ffn_b1, ffn_b1, nullptr, ffnh, NTOK, DFFN, DEMB);
    tgemm<0, true, false><<<gProj, 256, GSMEM>>>(ffnh, ffnh, ffnh, wh + (size_t)12*WME,
        ffn_b2, ffn_b2, ffn_b2, ln2, res, NTOK, DEMB, DFFN);
    ln_kernel<false><<<NTOK, 256>>>(res, ln3_g, ln3_b, out, nullptr);
}

// round 17
// speedup vs baseline: 1.2722x; 1.0071x over previous
#include <cuda_runtime.h>
#include <cuda_fp16.h>
#include <cstdint>
#include <cstddef>

// Problem constants
#define BQ 4
#define SEQ 1024
#define DEMB 1024
#define NHEAD 16
#define DRED 64
#define NTOK (BQ*SEQ)          // 4096
#define DFFN (4*DEMB)          // 4096
#define BHSR ((size_t)BQ*NHEAD*SEQ*DRED)   // 4M

// ---------------------------------------------------------------------------
// Scratch (static device memory; no allocations anywhere)
// ---------------------------------------------------------------------------
__device__ float  g_res [(size_t)NTOK*DEMB];
__device__ __half g_xh  [(size_t)NTOK*DEMB];
__device__ __half g_ctxh[(size_t)NTOK*DEMB];
__device__ __half g_ln1h[(size_t)NTOK*DEMB];
__device__ __half g_ln2h[(size_t)NTOK*DEMB];
__device__ __half g_atth[(size_t)NTOK*DEMB];
__device__ __half g_ffnh[(size_t)NTOK*DFFN];
__device__ __half g_qkvh[(size_t)3*BHSR];

// fp16 weight scratch: transposed [N,K].
#define WME (1024*1024)
__device__ __half g_wh[(size_t)16*WME];

// ---------------------------------------------------------------------------
// PTX helpers (baseline PTX only)
// ---------------------------------------------------------------------------
__device__ __forceinline__ uint32_t smem_to_u32(const void* p) {
    uint32_t a;
    asm("{ .reg .u64 t; cvta.to.shared.u64 t, %1; cvt.u32.u64 %0, t; }"
        : "=r"(a) : "l"(p));
    return a;
}
__device__ __forceinline__ void cp_async16(uint32_t s, const void* g) {
    asm volatile("cp.async.cg.shared.global [%0], [%1], 16;" :: "r"(s), "l"(g));
}
#define CP_COMMIT() asm volatile("cp.async.commit_group;" ::: "memory")
#define CP_WAIT0()  asm volatile("cp.async.wait_group 0;" ::: "memory")
#define CP_WAIT1()  asm volatile("cp.async.wait_group 1;" ::: "memory")

__device__ __forceinline__ void ldm_x4(uint32_t* r, uint32_t addr) {
    asm volatile("ldmatrix.sync.aligned.m8n8.x4.shared.b16 {%0,%1,%2,%3}, [%4];"
        : "=r"(r[0]), "=r"(r[1]), "=r"(r[2]), "=r"(r[3]) : "r"(addr));
}
__device__ __forceinline__ void ldm_x4_t(uint32_t* r, uint32_t addr) {
    asm volatile("ldmatrix.sync.aligned.m8n8.x4.trans.shared.b16 {%0,%1,%2,%3}, [%4];"
        : "=r"(r[0]), "=r"(r[1]), "=r"(r[2]), "=r"(r[3]) : "r"(addr));
}
__device__ __forceinline__ void mma_f16(float* c, const uint32_t* a,
                                        uint32_t b0, uint32_t b1) {
    asm volatile(
        "mma.sync.aligned.m16n8k16.row.col.f32.f16.f16.f32 "
        "{%0,%1,%2,%3}, {%4,%5,%6,%7}, {%8,%9}, {%0,%1,%2,%3};"
        : "+f"(c[0]), "+f"(c[1]), "+f"(c[2]), "+f"(c[3])
        : "r"(a[0]), "r"(a[1]), "r"(a[2]), "r"(a[3]), "r"(b0), "r"(b1));
}
__device__ __forceinline__ uint32_t pack_h2(float x, float y) {
    __half2 h = __floats2half2_rn(x, y);
    return *(uint32_t*)&h;
}

// ---------------------------------------------------------------------------
// Fused fp32 -> fp16 elementwise for x and ctx
// ---------------------------------------------------------------------------
__global__ __launch_bounds__(256)
void conv_h2(const float* __restrict__ a, const float* __restrict__ b,
             __half* __restrict__ oa, __half* __restrict__ ob)
{
    const float* in  = blockIdx.y ? b : a;
    __half* out      = blockIdx.y ? ob : oa;
    const size_t i = ((size_t)blockIdx.x * 256 + threadIdx.x) * 4;
    float4 v = *(const float4*)&in[i];
    *(__half2*)&out[i]     = __floats2half2_rn(v.x, v.y);
    *(__half2*)&out[i + 2] = __floats2half2_rn(v.z, v.w);
}

// ---------------------------------------------------------------------------
// Weight transpose + fp16 convert, generic [R,C] per z-block.
// ---------------------------------------------------------------------------
__global__ __launch_bounds__(256)
void wconv(const float* __restrict__ in, __half* __restrict__ oh, int R, int C)
{
    __shared__ float tile[32][33];
    const int bz = blockIdx.z;
    const float* ip = in + (size_t)bz * R * C;
    const int r0 = blockIdx.y * 32, c0 = blockIdx.x * 32;
    const int tx = threadIdx.x & 31;
    const int ty = threadIdx.x >> 5;

    #pragma unroll
    for (int i = 0; i < 32; i += 8)
        tile[ty + i][tx] = ip[(size_t)(r0 + ty + i) * C + c0 + tx];
    __syncthreads();

    #pragma unroll
    for (int i = 0; i < 32; i += 8) {
        float x = tile[tx][ty + i];
        size_t o = ((size_t)bz * C + c0 + ty + i) * R + r0 + tx;
        oh[o] = __float2half_rn(x);
    }
}

// Fused 2-matrix wconv (sa_wo + ca_wo, both 1024x1024)
__global__ __launch_bounds__(256)
void wconv2(const float* __restrict__ in0, const float* __restrict__ in1,
            __half* __restrict__ o0, __half* __restrict__ o1)
{
    __shared__ float tile[32][33];
    const float* in = blockIdx.z ? in1 : in0;
    __half* oh      = blockIdx.z ? o1  : o0;
    const int R = 1024, C = 1024;
    const int r0 = blockIdx.y * 32, c0 = blockIdx.x * 32;
    const int tx = threadIdx.x & 31;
    const int ty = threadIdx.x >> 5;

    #pragma unroll
    for (int i = 0; i < 32; i += 8)
        tile[ty + i][tx] = in[(size_t)(r0 + ty + i) * C + c0 + tx];
    __syncthreads();

    #pragma unroll
    for (int i = 0; i < 32; i += 8) {
        float x = tile[tx][ty + i];
        size_t o = ((size_t)(c0 + ty + i)) * R + r0 + tx;
        oh[o] = __float2half_rn(x);
    }
}

// Fused 6-way wconv for both QKV triples ([H,D,R], H=16 blocks of 1024x64)
__global__ __launch_bounds__(256)
void wconv6(const float* __restrict__ w0, const float* __restrict__ w1,
            const float* __restrict__ w2, const float* __restrict__ w3,
            const float* __restrict__ w4, const float* __restrict__ w5,
            __half* __restrict__ oh)
{
    __shared__ float tile[32][33];
    const int z   = blockIdx.z;            // 0..95
    const int grp = z >> 4;                // 0..5
    const int bz  = z & 15;
    const float* in = (grp == 0) ? w0 : (grp == 1) ? w1 : (grp == 2) ? w2
                    : (grp == 3) ? w3 : (grp == 4) ? w4 : w5;
    __half* out = oh + (size_t)((grp < 3) ? grp : grp + 1) * WME;
    const int R = 1024, C = 64;
    const float* ip = in + (size_t)bz * R * C;
    const int r0 = blockIdx.y * 32, c0 = blockIdx.x * 32;
    const int tx = threadIdx.x & 31;
    const int ty = threadIdx.x >> 5;

    #pragma unroll
    for (int i = 0; i < 32; i += 8)
        tile[ty + i][tx] = ip[(size_t)(r0 + ty + i) * C + c0 + tx];
    __syncthreads();

    #pragma unroll
    for (int i = 0; i < 32; i += 8) {
        float x = tile[tx][ty + i];
        size_t o = ((size_t)bz * C + c0 + ty + i) * R + r0 + tx;
        out[o] = __float2half_rn(x);
    }
}

// ---------------------------------------------------------------------------
// Tensor-core GEMM (fp16 in, fp32 accumulate) — R12/R16 proven core.
// CTA 128x128, 256 threads, 8 warps of 32x64, BK=32, 2 x 20KB buffers.
// Schedule: issue c+1 -> compute c -> wait -> sync.
// OMODE 0: fp32 row-major.  1: fused-QKV fp16 [3][B,H,S,R].  2: fp16 row-major.
// RES:   0 none, 2 fp16 residual.
// ---------------------------------------------------------------------------
#define PITCH 80
#define OFF_W  10240
#define BUFSZ  20480
#define GSMEM  (2*BUFSZ)

template<int OMODE, int RES, bool RELU>
__global__ __launch_bounds__(256)
void tgemm(const __half* __restrict__ A0, const __half* __restrict__ A1,
           const __half* __restrict__ A2, const __half* __restrict__ W,
           const float* __restrict__ b0, const float* __restrict__ b1,
           const float* __restrict__ b2, const __half* __restrict__ resid,
           void* __restrict__ Cout, int M, int N, int K)
{
    extern __shared__ char smem[];
    const uint32_t sb = smem_to_u32(smem);

    const int t    = threadIdx.x;
    const int lane = t & 31;
    const int wid  = t >> 5;
    const int wm   = wid & 3;
    const int wn   = wid >> 2;
    const int m0   = blockIdx.y * 128;
    const int n0   = blockIdx.x * 128;
    const int nch  = K >> 5;

    const int which = (OMODE == 1) ? (n0 >> 10) : 0;
    const __half* A   = (which == 0) ? A0 : (which == 1) ? A1 : A2;
    const float* bias = (which == 0) ? b0 : (which == 1) ? b1 : b2;

    // A staging: row t>>1, 32B half (t&1)
    const uint32_t aDst = (uint32_t)(t >> 1) * PITCH + (t & 1) * 32;
    const __half*  aSrcBase = A + (size_t)(m0 + (t >> 1)) * K + (t & 1) * 16;
    // W staging: 2 16B chunks per thread
    const int q0r = (2 * t) >> 2,     q0c = (2 * t) & 3;
    const int q1r = (2 * t + 1) >> 2, q1c = (2 * t + 1) & 3;

    float acc[2][8][4];
    #pragma unroll
    for (int a = 0; a < 2; a++)
        #pragma unroll
        for (int b = 0; b < 8; b++)
            #pragma unroll
            for (int d = 0; d < 4; d++) acc[a][b][d] = 0.f;

    auto loadAW = [&](int k0, uint32_t bufo) {
        cp_async16(sb + bufo + aDst,      aSrcBase + k0);
        cp_async16(sb + bufo + aDst + 16, aSrcBase + k0 + 8);
        cp_async16(sb + bufo + OFF_W + q0r * PITCH + q0c * 16,
                   W + (size_t)(n0 + q0r) * K + k0 + q0c * 8);
        cp_async16(sb + bufo + OFF_W + q1r * PITCH + q1c * 16,
                   W + (size_t)(n0 + q1r) * K + k0 + q1c * 8);
        CP_COMMIT();
    };

    const uint32_t aBase = sb + (uint32_t)(wm * 32 + (lane & 15)) * PITCH + (lane >> 4) * 16;
    const uint32_t wBase = sb + OFF_W
        + (uint32_t)(wn * 64 + ((lane >> 4) << 3) + (lane & 7)) * PITCH
        + ((lane >> 3) & 1) * 16;

    auto compute = [&](uint32_t bufo) {
        #pragma unroll
        for (int ks = 0; ks < 2; ks++) {
            uint32_t ah[2][4];
            #pragma unroll
            for (int mt = 0; mt < 2; mt++)
                ldm_x4(ah[mt], aBase + bufo + mt * (16*PITCH) + ks * 32);
            #pragma unroll
            for (int ng = 0; ng < 2; ng++) {
                uint32_t bh[8];
                #pragma unroll
                for (int p = 0; p < 2; p++)
                    ldm_x4(bh + p*4, wBase + bufo + (ng*2 + p) * (16*PITCH) + ks * 32);
                #pragma unroll
                for (int nt = 0; nt < 4; nt++)
                    #pragma unroll
                    for (int mt = 0; mt < 2; mt++)
                        mma_f16(acc[mt][ng*4 + nt], ah[mt], bh[nt*2], bh[nt*2+1]);
            }
        }
    };

    loadAW(0, 0);
    CP_WAIT0();
    __syncthreads();

    for (int c = 0; c < nch; c++) {
        const uint32_t bufo = (c & 1) * BUFSZ;
        const bool hasNext = (c + 1 < nch);
        if (hasNext) loadAW((c + 1) << 5, BUFSZ - bufo);
        compute(bufo);
        if (hasNext) CP_WAIT0();
        __syncthreads();
    }

    // ---- epilogue ----
    #pragma unroll
    for (int mt = 0; mt < 2; mt++) {
        const int m = m0 + wm * 32 + mt * 16 + (lane >> 2);
        #pragma unroll
        for (int j = 0; j < 8; j++) {
            const int n = n0 + wn * 64 + j * 8 + (lane & 3) * 2;
            const int nb = (OMODE == 1) ? (n & 1023) : n;
            float2 v0 = make_float2(acc[mt][j][0], acc[mt][j][1]);
            float2 v1 = make_float2(acc[mt][j][2], acc[mt][j][3]);
            float2 b2v = *(const float2*)&bias[nb];
            v0.x += b2v.x; v0.y += b2v.y;
            v1.x += b2v.x; v1.y += b2v.y;
            if (RES == 2) {
                __half2 r0 = *(const __half2*)&resid[(size_t)m * N + n];
                __half2 r1 = *(const __half2*)&resid[(size_t)(m + 8) * N + n];
                float2 f0 = __half22float2(r0);
                float2 f1 = __half22float2(r1);
                v0.x += f0.x; v0.y += f0.y;
                v1.x += f1.x; v1.y += f1.y;
            }
            if (RELU) {
                v0.x = fmaxf(v0.x, 0.f); v0.y = fmaxf(v0.y, 0.f);
                v1.x = fmaxf(v1.x, 0.f); v1.y = fmaxf(v1.y, 0.f);
            }
            if (OMODE == 0) {
                float* C = (float*)Cout;
                *(float2*)&C[(size_t)m * N + n]       = v0;
                *(float2*)&C[(size_t)(m + 8) * N + n] = v1;
            } else if (OMODE == 2) {
                __half* C = (__half*)Cout;
                *(__half2*)&C[(size_t)m * N + n]       = __floats2half2_rn(v0.x, v0.y);
                *(__half2*)&C[(size_t)(m + 8) * N + n] = __floats2half2_rn(v1.x, v1.y);
            } else {
                __half* C = (__half*)Cout;
                const int h = nb >> 6, r = nb & 63;
                size_t o0 = (size_t)which * BHSR
                          + ((size_t)((m >> 10) * NHEAD + h) * SEQ + (m & (SEQ-1))) * DRED + r;
                size_t o1 = (size_t)which * BHSR
                          + ((size_t)(((m+8) >> 10) * NHEAD + h) * SEQ + ((m+8) & (SEQ-1))) * DRED + r;
                *(__half2*)&C[o0] = __floats2half2_rn(v0.x, v0.y);
                *(__half2*)&C[o1] = __floats2half2_rn(v1.x, v1.y);
            }
        }
    }
}

// ---------------------------------------------------------------------------
// Tensor-core flash attention (fp16 in/out), Q-hoisted + double-buffered K/V.
// (exact R16 version)
// ---------------------------------------------------------------------------
#define APITCH 144
#define AKV    36864
#define ASMEM  92160

__global__ __launch_bounds__(256)
void attn_tc(const __half* __restrict__ QKV, __half* __restrict__ Out)
{
    extern __shared__ char sm[];
    const uint32_t sb = smem_to_u32(sm);

    const int t    = threadIdx.x;
    const int lane = t & 31;
    const int w    = t >> 5;
    const int bh   = blockIdx.y;
    const int b    = bh >> 4;
    const int h    = bh & 15;
    const int q0   = blockIdx.x * 128;

    const size_t base = (size_t)bh * SEQ * DRED;
    const __half* Qb = QKV + base;
    const __half* Kb = QKV + BHSR + base;
    const __half* Vb = QKV + 2 * BHSR + base;

    const int lrow  = t >> 1;
    const int lhalf = t & 1;
    auto stage = [&](const __half* src, uint32_t dst) {
        const __half* g = src + (size_t)lrow * DRED + lhalf * 32;
        uint32_t d = sb + dst + (uint32_t)lrow * APITCH + lhalf * 64;
        cp_async16(d,      g);
        cp_async16(d + 16, g + 8);
        cp_async16(d + 32, g + 16);
        cp_async16(d + 48, g + 24);
    };
    auto stageKV = [&](int kt, int buf) {
        uint32_t o = 18432 + (uint32_t)buf * AKV;
        stage(Kb + (size_t)(kt * 128) * DRED, o);
        stage(Vb + (size_t)(kt * 128) * DRED, o + 18432);
        CP_COMMIT();
    };

    stage(Qb + (size_t)q0 * DRED, 0);
    CP_COMMIT();

    const uint32_t aOff = (uint32_t)(w * 16 + (lane & 15)) * APITCH + (lane >> 4) * 16;
    const uint32_t kRow = ((lane >> 4) << 3) + (lane & 7);
    const uint32_t kCol = ((lane >> 3) & 1) * 16;

    uint32_t qh[4][4];
    {
        CP_WAIT0();
        __syncthreads();
        #pragma unroll
        for (int ks = 0; ks < 4; ks++)
            ldm_x4(qh[ks], sb + aOff + ks * 32);
        __syncthreads();
    }

    stageKV(0, 0);

    float S[16][4];
    float O[8][4];
    float m0 = -1e30f, m1 = -1e30f, l0 = 0.f, l1 = 0.f;
    #pragma unroll
    for (int j = 0; j < 8; j++)
        #pragma unroll
        for (int d = 0; d < 4; d++) O[j][d] = 0.f;

    for (int kt = 0; kt < SEQ / 128; kt++) {
        const int buf = kt & 1;
        if (kt + 1 < SEQ / 128) {
            stageKV(kt + 1, buf ^ 1);
            CP_WAIT1();
        } else {
            CP_WAIT0();
        }
        __syncthreads();

        const uint32_t SK = 18432 + (uint32_t)buf * AKV;
        const uint32_t SV = SK + 18432;

        // ---- S = Q K^T ----
        #pragma unroll
        for (int j = 0; j < 16; j++) {
            S[j][0] = 0.f; S[j][1] = 0.f; S[j][2] = 0.f; S[j][3] = 0.f;
        }
        #pragma unroll
        for (int ks = 0; ks < 4; ks++) {
            #pragma unroll
            for (int np = 0; np < 8; np++) {
                uint32_t off = (uint32_t)(np * 16 + kRow) * APITCH + kCol + ks * 32;
                uint32_t bh4[4];
                ldm_x4(bh4, sb + SK + off);
                #pragma unroll
                for (int nt = 0; nt < 2; nt++)
                    mma_f16(S[np * 2 + nt], qh[ks], bh4[nt*2], bh4[nt*2+1]);
            }
        }

        // ---- online softmax ----
        float mx0 = -1e30f, mx1 = -1e30f;
        #pragma unroll
        for (int j = 0; j < 16; j++) {
            S[j][0] *= 0.125f; S[j][1] *= 0.125f;
            S[j][2] *= 0.125f; S[j][3] *= 0.125f;
            mx0 = fmaxf(mx0, fmaxf(S[j][0], S[j][1]));
            mx1 = fmaxf(mx1, fmaxf(S[j][2], S[j][3]));
        }
        mx0 = fmaxf(mx0, __shfl_xor_sync(0xffffffffu, mx0, 1));
        mx0 = fmaxf(mx0, __shfl_xor_sync(0xffffffffu, mx0, 2));
        mx1 = fmaxf(mx1, __shfl_xor_sync(0xffffffffu, mx1, 1));
        mx1 = fmaxf(mx1, __shfl_xor_sync(0xffffffffu, mx1, 2));
        float mn0 = fmaxf(m0, mx0), mn1 = fmaxf(m1, mx1);
        float a0 = __expf(m0 - mn0), a1 = __expf(m1 - mn1);
        m0 = mn0; m1 = mn1;
        float rs0 = 0.f, rs1 = 0.f;
        #pragma unroll
        for (int j = 0; j < 16; j++) {
            float p0 = __expf(S[j][0] - mn0); S[j][0] = p0; rs0 += p0;
            float p1 = __expf(S[j][1] - mn0); S[j][1] = p1; rs0 += p1;
            float p2 = __expf(S[j][2] - mn1); S[j][2] = p2; rs1 += p2;
            float p3 = __expf(S[j][3] - mn1); S[j][3] = p3; rs1 += p3;
        }
        l0 = l0 * a0 + rs0;
        l1 = l1 * a1 + rs1;
        #pragma unroll
        for (int j = 0; j < 8; j++) {
            O[j][0] *= a0; O[j][1] *= a0;
            O[j][2] *= a1; O[j][3] *= a1;
        }

        // ---- O += P V ----
        #pragma unroll
        for (int ks = 0; ks < 8; ks++) {
            uint32_t ah[4];
            ah[0] = pack_h2(S[2*ks][0],   S[2*ks][1]);
            ah[1] = pack_h2(S[2*ks][2],   S[2*ks][3]);
            ah[2] = pack_h2(S[2*ks+1][0], S[2*ks+1][1]);
            ah[3] = pack_h2(S[2*ks+1][2], S[2*ks+1][3]);
            #pragma unroll
            for (int np = 0; np < 4; np++) {
                uint32_t off = (uint32_t)(ks * 16 + ((lane >> 3) & 1) * 8 + (lane & 7)) * APITCH
                             + (np * 16 + (lane >> 4) * 8) * 2;
                uint32_t bh4[4];
                ldm_x4_t(bh4, sb + SV + off);
                #pragma unroll
                for (int nt = 0; nt < 2; nt++)
                    mma_f16(O[np * 2 + nt], ah, bh4[nt*2], bh4[nt*2+1]);
            }
        }
        __syncthreads();
    }

    // ---- finalize ----
    l0 += __shfl_xor_sync(0xffffffffu, l0, 1);
    l0 += __shfl_xor_sync(0xffffffffu, l0, 2);
    l1 += __shfl_xor_sync(0xffffffffu, l1, 1);
    l1 += __shfl_xor_sync(0xffffffffu, l1, 2);
    const float inv0 = 1.f / l0, inv1 = 1.f / l1;

    const int r0 = q0 + w * 16 + (lane >> 2);
    const size_t tok0 = (size_t)b * SEQ + r0;
    const size_t tok1 = tok0 + 8;
    #pragma unroll
    for (int ng = 0; ng < 8; ng++) {
        const int col = h * DRED + ng * 8 + (lane & 3) * 2;
        *(__half2*)&Out[tok0 * DEMB + col] = __floats2half2_rn(O[ng][0] * inv0, O[ng][1] * inv0);
        *(__half2*)&Out[tok1 * DEMB + col] = __floats2half2_rn(O[ng][2] * inv1, O[ng][3] * inv1);
    }
}

// ---------------------------------------------------------------------------
// LayerNorm over rows of 1024, eps = 1e-3.
// FINAL=false: write only fp16 (feeds next-stage GEMM A and fp16 residual).
// FINAL=true:  write only fp32 (model output).
// ---------------------------------------------------------------------------
template<bool FINAL>
__global__ __launch_bounds__(256)
void ln_kernel(const float* __restrict__ in, const float* __restrict__ gam,
               const float* __restrict__ bet, float* __restrict__ out,
               __half* __restrict__ outh)
{
    __shared__ float red[16];
    const int row = blockIdx.x;
    const int t   = threadIdx.x;
    const float* p = in + (size_t)row * DEMB;

    float4 v = *(const float4*)&p[t * 4];
    float s  = v.x + v.y + v.z + v.w;
    float ss = v.x * v.x + v.y * v.y + v.z * v.z + v.w * v.w;
    #pragma unroll
    for (int o = 16; o >= 1; o >>= 1) {
        s  += __shfl_xor_sync(0xffffffffu, s, o);
        ss += __shfl_xor_sync(0xffffffffu, ss, o);
    }
    if ((t & 31) == 0) { red[t >> 5] = s; red[8 + (t >> 5)] = ss; }
    __syncthreads();
    s = 0.f; ss = 0.f;
    #pragma unroll
    for (int i = 0; i < 8; i++) { s += red[i]; ss += red[8 + i]; }

    float mean = s * (1.f / DEMB);
    float var  = ss * (1.f / DEMB) - mean * mean;
    float r    = rsqrtf(var + 1e-3f);

    float4 g4 = *(const float4*)&gam[t * 4];
    float4 b4 = *(const float4*)&bet[t * 4];
    float4 o;
    o.x = (v.x - mean) * r * g4.x + b4.x;
    o.y = (v.y - mean) * r * g4.y + b4.y;
    o.z = (v.z - mean) * r * g4.z + b4.z;
    o.w = (v.w - mean) * r * g4.w + b4.w;
    if (FINAL) {
        *(float4*)&out[(size_t)row * DEMB + t * 4] = o;
    } else {
        *(__half2*)&outh[(size_t)row * DEMB + t * 4]     = __floats2half2_rn(o.x, o.y);
        *(__half2*)&outh[(size_t)row * DEMB + t * 4 + 2] = __floats2half2_rn(o.z, o.w);
    }
}

// ---------------------------------------------------------------------------
// Launch
// ---------------------------------------------------------------------------
extern "C" void kernel_launch(void* const* d_in, const int* in_sizes, int n_in,
                              void* d_out, int out_size)
{
    const float* x      = (const float*)d_in[0];
    const float* ctx    = (const float*)d_in[1];
    const float* sa_wq  = (const float*)d_in[2];
    const float* sa_bq  = (const float*)d_in[3];
    const float* sa_wk  = (const float*)d_in[4];
    const float* sa_bk  = (const float*)d_in[5];
    const float* sa_wv  = (const float*)d_in[6];
    const float* sa_bv  = (const float*)d_in[7];
    const float* sa_wo  = (const float*)d_in[8];
    const float* sa_bo  = (const float*)d_in[9];
    const float* ca_wq  = (const float*)d_in[10];
    const float* ca_bq  = (const float*)d_in[11];
    const float* ca_wk  = (const float*)d_in[12];
    const float* ca_bk  = (const float*)d_in[13];
    const float* ca_wv  = (const float*)d_in[14];
    const float* ca_bv  = (const float*)d_in[15];
    const float* ca_wo  = (const float*)d_in[16];
    const float* ca_bo  = (const float*)d_in[17];
    const float* ln1_g  = (const float*)d_in[18];
    const float* ln1_b  = (const float*)d_in[19];
    const float* ln2_g  = (const float*)d_in[20];
    const float* ln2_b  = (const float*)d_in[21];
    const float* ln3_g  = (const float*)d_in[22];
    const float* ln3_b  = (const float*)d_in[23];
    const float* ffn_w1 = (const float*)d_in[24];
    const float* ffn_b1 = (const float*)d_in[25];
    const float* ffn_w2 = (const float*)d_in[26];
    const float* ffn_b2 = (const float*)d_in[27];
    float* out = (float*)d_out;

    float *res;
    __half *xh, *ctxh, *ln1h, *ln2h, *atth, *ffnh, *qkvh, *wh;
    cudaGetSymbolAddress((void**)&res,  g_res);
    cudaGetSymbolAddress((void**)&xh,   g_xh);
    cudaGetSymbolAddress((void**)&ctxh, g_ctxh);
    cudaGetSymbolAddress((void**)&ln1h, g_ln1h);
    cudaGetSymbolAddress((void**)&ln2h, g_ln2h);
    cudaGetSymbolAddress((void**)&atth, g_atth);
    cudaGetSymbolAddress((void**)&ffnh, g_ffnh);
    cudaGetSymbolAddress((void**)&qkvh, g_qkvh);
    cudaGetSymbolAddress((void**)&wh,   g_wh);

    cudaFuncSetAttribute(tgemm<1, 0, false>, cudaFuncAttributeMaxDynamicSharedMemorySize, GSMEM);
    cudaFuncSetAttribute(tgemm<0, 2, false>, cudaFuncAttributeMaxDynamicSharedMemorySize, GSMEM);
    cudaFuncSetAttribute(tgemm<2, 0, true >, cudaFuncAttributeMaxDynamicSharedMemorySize, GSMEM);
    cudaFuncSetAttribute(attn_tc, cudaFuncAttributeMaxDynamicSharedMemorySize, ASMEM);

    // ---- conversions (5 launches) ----
    dim3 gc(NTOK * DEMB / 1024, 2);
    conv_h2<<<gc, 256>>>(x, ctx, xh, ctxh);
    dim3 tp6(2, 32, 96);
    wconv6<<<tp6, 256>>>(sa_wq, sa_wk, sa_wv, ca_wq, ca_wk, ca_wv, wh);
    dim3 tpO(32, 32, 2);
    wconv2<<<tpO, 256>>>(sa_wo, ca_wo, wh + (size_t)3*WME, wh + (size_t)7*WME);
    dim3 tpF1(128, 32, 1);
    wconv<<<tpF1, 256>>>(ffn_w1, wh + (size_t)8*WME,  1024, 4096);
    dim3 tpF2(32, 128, 1);
    wconv<<<tpF2, 256>>>(ffn_w2, wh + (size_t)12*WME, 4096, 1024);

    dim3 gQKV(3 * DEMB / 128, NTOK / 128);   // (24, 32)
    dim3 gProj(DEMB / 128, NTOK / 128);      // (8, 32)
    dim3 gFfn1(DFFN / 128, NTOK / 128);      // (32, 32)
    dim3 gAttn(SEQ / 128, BQ * NHEAD);       // (8, 64)

    // ---- self attention ----
    tgemm<1, 0, false><<<gQKV, 256, GSMEM>>>(xh, xh, xh, wh + (size_t)0*WME,
        sa_bq, sa_bk, sa_bv, nullptr, qkvh, NTOK, 3*DEMB, DEMB);
    attn_tc<<<gAttn, 256, ASMEM>>>(qkvh, atth);
    tgemm<0, 2, false><<<gProj, 256, GSMEM>>>(atth, atth, atth, wh + (size_t)3*WME,
        sa_bo, sa_bo, sa_bo, xh, res, NTOK, DEMB, DEMB);
    ln_kernel<false><<<NTOK, 256>>>(res, ln1_g, ln1_b, nullptr, ln1h);

    // ---- cross attention ----
    tgemm<1, 0, false><<<gQKV, 256, GSMEM>>>(ln1h, ctxh, ctxh, wh + (size_t)4*WME,
        ca_bq, ca_bk, ca_bv, nullptr, qkvh, NTOK, 3*DEMB, DEMB);
    attn_tc<<<gAttn, 256, ASMEM>>>(qkvh, atth);
    tgemm<0, 2, false><<<gProj, 256, GSMEM>>>(atth, atth, atth, wh + (size_t)7*WME,
        ca_bo, ca_bo, ca_bo, ln1h, res, NTOK, DEMB, DEMB);
    ln_kernel<false><<<NTOK, 256>>>(res, ln2_g, ln2_b, nullptr, ln2h);

    // ---- FFN ----
    tgemm<2, 0, true><<<gFfn1, 256, GSMEM>>>(ln2h, ln2h, ln2h, wh + (size_t)8*WME,
        ffn_b1, ffn_b1, ffn_b1, nullptr, ffnh, NTOK, DFFN, DEMB);
    tgemm<0, 2, false><<<gProj, 256, GSMEM>>>(ffnh, ffnh, ffnh, wh + (size_t)12*WME,
        ffn_b2, ffn_b2, ffn_b2, ln2h, res, NTOK, DEMB, DFFN);
    ln_kernel<true><<<NTOK, 256>>>(res, ln3_g, ln3_b, out, nullptr);
}